// round 11
// baseline (speedup 1.0000x reference)
#include <cuda_runtime.h>
#include <cuda_bf16.h>
#include <cstdint>

// Problem constants
#define BS       32
#define SEQ_LEN  4096
#define HIDDEN   1024
#define TPB      256
#define VPT      4          // outputs per thread (contiguous -> one STG.128)

__device__ __forceinline__ unsigned rotl32(unsigned x, int r) {
    return (x << r) | (x >> (32 - r));
}

__device__ __forceinline__ unsigned threefry_bits(unsigned j) {
    const unsigned k0 = 0u;
    const unsigned k1 = 42u;
    const unsigned k2 = k0 ^ k1 ^ 0x1BD11BDAu;
    unsigned x0 = 0u + k0;
    unsigned x1 = j  + k1;
    #define TF_ROUND(r) { x0 += x1; x1 = rotl32(x1, (r)); x1 ^= x0; }
    TF_ROUND(13) TF_ROUND(15) TF_ROUND(26) TF_ROUND(6)
    x0 += k1; x1 += k2 + 1u;
    TF_ROUND(17) TF_ROUND(29) TF_ROUND(16) TF_ROUND(24)
    x0 += k2; x1 += k0 + 2u;
    TF_ROUND(13) TF_ROUND(15) TF_ROUND(26) TF_ROUND(6)
    x0 += k0; x1 += k1 + 3u;
    TF_ROUND(17) TF_ROUND(29) TF_ROUND(16) TF_ROUND(24)
    x0 += k1; x1 += k2 + 4u;
    TF_ROUND(13) TF_ROUND(15) TF_ROUND(26) TF_ROUND(6)
    x0 += k2; x1 += k0 + 5u;
    #undef TF_ROUND
    return x0 ^ x1;
}

// One CTA per batch row; 256 threads; thread t owns emb [4t, 4t+4).
// No smem, no __syncthreads: each WARP redundantly sums the full mask top half
// (16 int4 per lane = 512 int4 = 2048 ints). Same addresses across warps ->
// warps 1..7 hit L1/L2 on warp 0's lines.
// Lengths are in [2048, 4096] -> mask[0:2048) is all ones; scan only the top half.
__global__ void __launch_bounds__(TPB, 1)
condensed_embracement_kernel(const float* __restrict__ tokens,
                             const int*   __restrict__ mask,
                             float*       __restrict__ out) {
    const int b    = blockIdx.x;
    const int t    = threadIdx.x;
    const int lane = t & 31;

    // ---- Phase 1 load: 2048 ints over [2048,4096); 16 int4 per LANE ----
    const int4* m4 =
        reinterpret_cast<const int4*>(mask + (size_t)b * SEQ_LEN + 2048);
    int s = 0;
    #pragma unroll
    for (int i = 0; i < 16; i++) {
        const int4 v = __ldg(&m4[lane + i * 32]);
        s += v.x + v.y + v.z + v.w;
    }

    // ---- 4 independent threefries (fill the load shadow, full ILP) ----
    unsigned bits[VPT];
    #pragma unroll
    for (int k = 0; k < VPT; k++)
        bits[k] = threefry_bits((unsigned)(b * HIDDEN + VPT * t + k));

    // ---- Warp-local reduce: prefix = 2048 + sum(top half); no barrier ----
    s = __reduce_add_sync(0xffffffffu, s);          // REDUX.SUM per warp

    const int prefix  = 2048 + s;
    const int n_valid = max(prefix - 1, 1);
    const float nvf   = (float)n_valid;

    // ---- Phase 2: 4 scattered gathers (MLP=4) -> one STG.128 ----
    const float* trow = tokens + (size_t)b * SEQ_LEN * HIDDEN;
    float4 r;
    float* rp = &r.x;
    #pragma unroll
    for (int k = 0; k < VPT; k++) {
        const int e = VPT * t + k;
        // uniform in [0,1): bitcast((bits>>9)|0x3f800000) - 1.0f (JAX-exact)
        const float u = __fsub_rn(
            __uint_as_float((bits[k] >> 9) | 0x3f800000u), 1.0f);
        int idx = (int)__fmul_rn(u, nvf);
        idx = min(idx, n_valid - 1);
        rp[k] = __ldg(&trow[(size_t)idx * HIDDEN + e]);
    }
    reinterpret_cast<float4*>(out + (size_t)b * HIDDEN)[t] = r;
}

extern "C" void kernel_launch(void* const* d_in, const int* in_sizes, int n_in,
                              void* d_out, int out_size) {
    // Defensive input dispatch by element count (tokens = 32*4096*1024).
    const float* tokens;
    const int*   mask;
    if (in_sizes[0] == BS * SEQ_LEN * HIDDEN) {
        tokens = (const float*)d_in[0];
        mask   = (const int*)d_in[1];
    } else {
        tokens = (const float*)d_in[1];
        mask   = (const int*)d_in[0];
    }
    float* out = (float*)d_out;   // (32, 1024) fp32
    (void)n_in; (void)out_size;

    condensed_embracement_kernel<<<BS, TPB>>>(tokens, mask, out);
}

// round 12
// speedup vs baseline: 1.0337x; 1.0337x over previous
#include <cuda_runtime.h>
#include <cuda_bf16.h>
#include <cstdint>

// Problem constants
#define BS       32
#define SEQ_LEN  4096
#define HIDDEN   1024
#define TPB      256
#define VPT      4          // outputs per thread (contiguous -> one STG.128)
#define NWARP    (TPB / 32)

__device__ __forceinline__ unsigned rotl32(unsigned x, int r) {
    return (x << r) | (x >> (32 - r));
}

__device__ __forceinline__ unsigned threefry_bits(unsigned j) {
    const unsigned k0 = 0u;
    const unsigned k1 = 42u;
    const unsigned k2 = k0 ^ k1 ^ 0x1BD11BDAu;
    unsigned x0 = 0u + k0;
    unsigned x1 = j  + k1;
    #define TF_ROUND(r) { x0 += x1; x1 = rotl32(x1, (r)); x1 ^= x0; }
    TF_ROUND(13) TF_ROUND(15) TF_ROUND(26) TF_ROUND(6)
    x0 += k1; x1 += k2 + 1u;
    TF_ROUND(17) TF_ROUND(29) TF_ROUND(16) TF_ROUND(24)
    x0 += k2; x1 += k0 + 2u;
    TF_ROUND(13) TF_ROUND(15) TF_ROUND(26) TF_ROUND(6)
    x0 += k0; x1 += k1 + 3u;
    TF_ROUND(17) TF_ROUND(29) TF_ROUND(16) TF_ROUND(24)
    x0 += k1; x1 += k2 + 4u;
    TF_ROUND(13) TF_ROUND(15) TF_ROUND(26) TF_ROUND(6)
    x0 += k2; x1 += k0 + 5u;
    #undef TF_ROUND
    return x0 ^ x1;
}

// One CTA per batch row; 256 threads; thread t owns emb [4t, 4t+4).
// Phase 1: block-wide sum of the mask top half (2 int4/thread, no redundancy),
// REDUX.SUM per warp + one smem round-trip + one __syncthreads (R9 structure —
// measured fastest).  Lengths in [2048,4096] -> mask[0:2048) is all ones.
__global__ void __launch_bounds__(TPB, 1)
condensed_embracement_kernel(const float* __restrict__ tokens,
                             const int*   __restrict__ mask,
                             float*       __restrict__ out) {
    const int b = blockIdx.x;
    const int t = threadIdx.x;

    // ---- Phase 1 load: 2048 ints over [2048,4096), two int4 per thread ----
    const int4* m4 =
        reinterpret_cast<const int4*>(mask + (size_t)b * SEQ_LEN + 2048);
    const int4 a0 = __ldg(&m4[t]);
    const int4 a1 = __ldg(&m4[t + TPB]);

    // ---- 4 independent threefries (fill the load shadow, full ILP) ----
    unsigned bits[VPT];
    #pragma unroll
    for (int k = 0; k < VPT; k++)
        bits[k] = threefry_bits((unsigned)(b * HIDDEN + VPT * t + k));

    // ---- Phase 1 reduce: prefix = 2048 + sum(top half) ----
    int s = a0.x + a0.y + a0.z + a0.w + a1.x + a1.y + a1.z + a1.w;
    s = __reduce_add_sync(0xffffffffu, s);          // REDUX.SUM per warp

    __shared__ int wsum[NWARP];
    if ((t & 31) == 0) wsum[t >> 5] = s;
    __syncthreads();
    int prefix = 2048;
    #pragma unroll
    for (int w = 0; w < NWARP; w++) prefix += wsum[w];

    const int n_valid = max(prefix - 1, 1);
    const float nvf   = (float)n_valid;

    // ---- Phase 2: 4 scattered gathers (MLP=4) -> one STG.128 ----
    const float* trow = tokens + (size_t)b * SEQ_LEN * HIDDEN;
    float4 r;
    float* rp = &r.x;
    #pragma unroll
    for (int k = 0; k < VPT; k++) {
        const int e = VPT * t + k;
        // uniform in [0,1): bitcast((bits>>9)|0x3f800000) - 1.0f (JAX-exact)
        const float u = __fsub_rn(
            __uint_as_float((bits[k] >> 9) | 0x3f800000u), 1.0f);
        int idx = (int)__fmul_rn(u, nvf);
        idx = min(idx, n_valid - 1);
        rp[k] = __ldg(&trow[(size_t)idx * HIDDEN + e]);
    }
    reinterpret_cast<float4*>(out + (size_t)b * HIDDEN)[t] = r;
}

extern "C" void kernel_launch(void* const* d_in, const int* in_sizes, int n_in,
                              void* d_out, int out_size) {
    // Defensive input dispatch by element count (tokens = 32*4096*1024).
    const float* tokens;
    const int*   mask;
    if (in_sizes[0] == BS * SEQ_LEN * HIDDEN) {
        tokens = (const float*)d_in[0];
        mask   = (const int*)d_in[1];
    } else {
        tokens = (const float*)d_in[1];
        mask   = (const int*)d_in[0];
    }
    float* out = (float*)d_out;   // (32, 1024) fp32
    (void)n_in; (void)out_size;

    condensed_embracement_kernel<<<BS, TPB>>>(tokens, mask, out);
}